// round 17
// baseline (speedup 1.0000x reference)
#include <cuda_runtime.h>
#include <cuda_fp16.h>
#include <cstdint>

// B=128, U=64, A=64. fp16 mma.sync m16n8k16 single plane; ldmatrix B operands.
// Permuted output channels (shuffle-free pack). gamma(i)+phi(i+1) FUSED:
// gamma writes r into smem H; phi conv1 consumes it directly (no gmem round-trip).

#define NBA 8192

__device__ float g_cgT[NBA * 64];
__device__ __align__(16) uint32_t g_rP[(size_t)NBA * 2048];
__device__ __align__(16) uint32_t g_msgsP[(size_t)NBA * 2048];
__device__ float g_sums[128 * 4096];
__device__ float g_P[128 * 4096];
__device__ __align__(16) uint32_t g_wfrag[45056];
__device__ float g_wcg[6 * 64];

#define O_PHI1_W2 0
#define O_PHIK_W1(i) (2048 + (i) * 2048)
#define O_PHIK_W2(i) (10240 + (i) * 2048)
#define O_G1_W1 18432
#define O_G1_W2 20480
#define O_GK_W1(i) (22528 + (i) * 4096)
#define O_GK_W2(i) (34816 + (i) * 2048)
#define O_G5_W1 40960

#define CP_ASYNC16(dst, src) asm volatile("cp.async.cg.shared.global [%0], [%1], 16;" :: "r"(dst), "l"(src))
#define CP_COMMIT()          asm volatile("cp.async.commit_group;" ::: "memory")
#define CP_WAIT1()           asm volatile("cp.async.wait_group 1;" ::: "memory")
#define CP_WAIT0()           asm volatile("cp.async.wait_group 0;" ::: "memory")
#define BARH(id)             asm volatile("bar.sync %0, 128;" :: "r"(id) : "memory")
#define LDM4(r0, r1, r2, r3, a) asm volatile( \
    "ldmatrix.sync.aligned.m8n8.x4.shared.b16 {%0,%1,%2,%3}, [%4];" \
    : "=r"(r0), "=r"(r1), "=r"(r2), "=r"(r3) : "r"(a))

__device__ __forceinline__ uint32_t packh(float lo, float hi) {
    return (uint32_t)__half_as_ushort(__float2half_rn(lo)) |
           ((uint32_t)__half_as_ushort(__float2half_rn(hi)) << 16);
}
__device__ __forceinline__ void mma16816(float d[4], const uint4& a, uint32_t b0, uint32_t b1) {
    asm volatile("mma.sync.aligned.m16n8k16.row.col.f32.f16.f16.f32 "
                 "{%0,%1,%2,%3}, {%4,%5,%6,%7}, {%8,%9}, {%0,%1,%2,%3};\n"
                 : "+f"(d[0]), "+f"(d[1]), "+f"(d[2]), "+f"(d[3])
                 : "r"(a.x), "r"(a.y), "r"(a.z), "r"(a.w), "r"(b0), "r"(b1));
}
__device__ __forceinline__ void colsum2(float acc[8][4], float& SA, float& SB) {
    SA = 0.f; SB = 0.f;
#pragma unroll
    for (int nt = 0; nt < 8; ++nt) { SA += acc[nt][0] + acc[nt][1]; SB += acc[nt][2] + acc[nt][3]; }
    SA += __shfl_xor_sync(0xffffffffu, SA, 1); SA += __shfl_xor_sync(0xffffffffu, SA, 2);
    SB += __shfl_xor_sync(0xffffffffu, SB, 1); SB += __shfl_xor_sync(0xffffffffu, SB, 2);
}

// ---------------- prep: fp16 A-fragments + wcg (verified R16, permuted rows) --
__global__ void prep_kernel(const float* __restrict__ phi1W1, const float* __restrict__ phi1W2,
                            const float* __restrict__ phiKW1, const float* __restrict__ phiKW2,
                            const float* __restrict__ g1W1,   const float* __restrict__ g1W2,
                            const float* __restrict__ gKW1,   const float* __restrict__ gKW2,
                            const float* __restrict__ g5W1) {
    const int id = blockIdx.x;
    if (id >= 18) {
        int w = id - 18, o = threadIdx.x;
        if (o < 64) {
            float v;
            if (w == 0) v = phi1W1[o * 2] + phi1W1[o * 2 + 1];
            else if (w <= 4) v = phiKW1[(w - 1) * 4160 + o * 65];
            else v = g1W1[o * 65];
            g_wcg[w * 64 + o] = v;
        }
        return;
    }
    const float* src; int off, KB, type;
    if (id == 0)       { src = phi1W2;              off = O_PHI1_W2;       KB = 4; type = 0; }
    else if (id < 5)   { int i = id - 1;  src = phiKW1 + i * 4160; off = O_PHIK_W1(i); KB = 4; type = 1; }
    else if (id < 9)   { int i = id - 5;  src = phiKW2 + i * 4096; off = O_PHIK_W2(i); KB = 4; type = 0; }
    else if (id == 9)  { src = g1W1;                off = O_G1_W1;         KB = 4; type = 4; }
    else if (id == 10) { src = g1W2;                off = O_G1_W2;         KB = 4; type = 0; }
    else if (id < 14)  { int i = id - 11; src = gKW1 + i * 8192;  off = O_GK_W1(i);  KB = 8; type = 5; }
    else if (id < 17)  { int i = id - 14; src = gKW2 + i * 4096;  off = O_GK_W2(i);  KB = 4; type = 0; }
    else               { src = g5W1;                off = O_G5_W1;         KB = 8; type = 5; }

    const float ninv = -1.0f / 63.0f;
    const int total = KB * 512;
    for (int e = threadIdx.x; e < total; e += blockDim.x) {
        int strip = e / (KB * 128);
        int rem   = e % (KB * 128);
        int kt = rem / 128;
        int r3 = rem & 127;
        int lane = r3 >> 2, j = r3 & 3;
        int o  = strip * 16 + 2 * (lane >> 2) + (j & 1);
        int k0 = kt * 16 + (lane & 3) * 2 + 8 * (j >> 1);
        float w0, w1;
        if (type == 0)      { w0 = src[o * 64 + k0];  w1 = src[o * 64 + k0 + 1]; }
        else if (type == 5) { w0 = src[o * 128 + k0]; w1 = src[o * 128 + k0 + 1];
                              if (k0 >= 64) { w0 *= ninv; w1 *= ninv; } }
        else if (type == 1) { w0 = src[o * 65 + 1 + k0]; w1 = src[o * 65 + 2 + k0]; }
        else                { w0 = src[o * 65 + 1 + k0] * ninv; w1 = src[o * 65 + 2 + k0] * ninv; }
        g_wfrag[off + e] = packh(w0, w1);
    }
}

__global__ void cgt_kernel(const float* __restrict__ cg) {
    const int b = blockIdx.x;
    for (int j = threadIdx.x; j < 4096; j += 256) {
        int a = j >> 6, u = j & 63;
        g_cgT[(b * 64 + a) * 64 + u] = cg[b * 4096 + u * 64 + a];
    }
}

__global__ void asum_kernel() {
    const int b = blockIdx.x >> 3;
    const int e = (blockIdx.x & 7) * 256 + threadIdx.x;
    const uint32_t* p0 = g_msgsP + (size_t)b * 131072 + e;
    float s0 = 0.f, s1 = 0.f;
#pragma unroll 8
    for (int a = 0; a < 64; ++a) {
        uint32_t h = p0[(size_t)a * 2048];
        __half2 hv = *reinterpret_cast<const __half2*>(&h);
        float2 f = __half22float2(hv);
        s0 += f.x; s1 += f.y;
    }
    int u = e >> 5, c2 = e & 31;
    g_sums[b * 4096 + (2 * c2) * 64 + u]     = s0;
    g_sums[b * 4096 + (2 * c2 + 1) * 64 + u] = s1;
}

__global__ void pP_kernel(const float* __restrict__ Wsrc, const float* __restrict__ b1,
                          int CW, int cOff) {
    __shared__ float sWT[64 * 65];
    __shared__ float sS2[4096];
    const int b = blockIdx.x, t = threadIdx.x;
    for (int idx = t; idx < 4096; idx += 256) {
        int o = idx >> 6, c = idx & 63;
        sWT[c * 65 + o] = Wsrc[o * CW + cOff + c] * (1.0f / 63.0f);
        sS2[idx] = g_sums[b * 4096 + idx];
    }
    __syncthreads();
    const int o = t & 63, ublk = t >> 6;
    float acc[16];
    float bv = __ldg(b1 + o);
#pragma unroll
    for (int i = 0; i < 16; ++i) acc[i] = bv;
    const float4* S4 = (const float4*)sS2;
#pragma unroll 4
    for (int c = 0; c < 64; ++c) {
        float w = sWT[c * 65 + o];
#pragma unroll
        for (int i = 0; i < 4; ++i) {
            float4 s = S4[c * 16 + ublk * 4 + i];
            acc[i * 4 + 0] += w * s.x; acc[i * 4 + 1] += w * s.y;
            acc[i * 4 + 2] += w * s.z; acc[i * 4 + 3] += w * s.w;
        }
    }
    float4* P4 = (float4*)(g_P + b * 4096 + o * 64 + ublk * 16);
#pragma unroll
    for (int i = 0; i < 4; ++i)
        P4[i] = make_float4(acc[i * 4], acc[i * 4 + 1], acc[i * 4 + 2], acc[i * 4 + 3]);
}

// ---------------- prefetch helpers -------------------------------------------
template<int MODE, int S1>
__device__ __forceinline__ void prefetch_slice(uint32_t dstB, int ba, int t2) {
    const uint32_t* rP = g_rP + (size_t)ba * 2048;
    const uint32_t* mP = g_msgsP + (size_t)ba * 2048;
    if (MODE == 3) {
        for (int cc = t2; cc < 64 * 16; cc += 128) {
            int row = cc >> 4, ch = cc & 15;
            const uint32_t* src = (ch < 8) ? (rP + row * 32 + ch * 4)
                                           : (mP + row * 32 + (ch - 8) * 4);
            CP_ASYNC16(dstB + (uint32_t)(row * S1 + ch * 4) * 4u, src);
        }
    } else {   // msgs only
        for (int cc = t2; cc < 64 * 8; cc += 128) {
            int row = cc >> 3, ch = cc & 7;
            CP_ASYNC16(dstB + (uint32_t)(row * S1 + ch * 4) * 4u, mP + row * 32 + ch * 4);
        }
    }
}

// ---------------- layer kernel (R16; used for phi1 and FINAL only) -----------
template<int KB1, int MODE, bool FINAL>
__global__ void __launch_bounds__(256, 2) layer_kernel(const float* __restrict__ b1v,
                                                       const float* __restrict__ b2v,
                                                       int w1off, int w2off, int wcgIdx,
                                                       const float* __restrict__ w2raw,
                                                       float* __restrict__ dout) {
    constexpr int S1 = KB1 * 8 + 4;
    constexpr int BUFU = (KB1 > 0) ? 64 * S1 : 0;
    constexpr int W1U = (KB1 > 0) ? KB1 * 512 : 0;
    extern __shared__ uint32_t sm[];
    uint32_t* sW1f = sm;
    uint32_t* sX   = sW1f + W1U;
    uint32_t* sH   = sX + 4 * BUFU;
    float*    sRed = (float*)sH;

    const int t = threadIdx.x;
    const int warp = t >> 5, lane = t & 31, q = lane & 3, g = lane >> 2;
    const int half = warp >> 2, wl = warp & 3;
    const int t2 = t & 127;
    const int o2 = wl * 16 + 2 * g, o2p = o2 + 1;
    const int c2i = wl * 8 + g;
    const float inv = 1.0f / 63.0f;
    const int barid = 1 + half;
    const int row_lane = (lane & 7) + ((lane >> 4) << 3);
    const int kb_off = ((lane >> 3) & 1) * 4;

    uint32_t smbase;
    asm("{ .reg .u64 tmp; cvta.to.shared.u64 tmp, %1; cvt.u32.u64 %0, tmp; }"
        : "=r"(smbase) : "l"(sm));
    const uint32_t xbyte = smbase + (uint32_t)W1U * 4u;
    const uint32_t hbyte = smbase + (uint32_t)(W1U + 4 * BUFU + half * 2304) * 4u;
    uint32_t* sHh = sH + half * 2304;

    if (KB1 > 0) {
        const uint4* gw1 = (const uint4*)(g_wfrag + w1off);
        uint4* d1 = (uint4*)sW1f;
        for (int i = t; i < KB1 * 128; i += 256) d1[i] = gw1[i];
    }
    uint4 W2r[4];
    if (!FINAL) {
        const uint4* gw2 = (const uint4*)(g_wfrag + w2off);
#pragma unroll
        for (int kt = 0; kt < 4; ++kt) W2r[kt] = gw2[wl * 128 + kt * 32 + lane];
    }
    float bA1 = 0.f, bB1 = 0.f, bA2 = 0.f, bB2 = 0.f, w2a = 0.f, w2b = 0.f, bF = 0.f;
    float wA = 0.f, wB = 0.f;
    if (MODE < 2)  { bA1 = __ldg(b1v + o2); bB1 = __ldg(b1v + o2p); }
    if (MODE <= 2) { wA = g_wcg[wcgIdx * 64 + o2]; wB = g_wcg[wcgIdx * 64 + o2p]; }
    if (!FINAL)    { bA2 = __ldg(b2v + o2); bB2 = __ldg(b2v + o2p); }
    if (FINAL)     { w2a = __ldg(w2raw + o2); w2b = __ldg(w2raw + o2p); bF = __ldg(b2v); }

    {
        int tot = 4 * BUFU + (FINAL ? 512 : 2 * 2304);
        for (int i = t; i < tot; i += 256) sX[i] = 0;
    }
    __syncthreads();

    const int stride2 = gridDim.x * 2;
    const int stream = blockIdx.x * 2 + half;
    int o = 0;
    if (KB1 > 0) {
        if (stream < NBA)
            prefetch_slice<MODE, S1>(xbyte + (uint32_t)((half * 2) * BUFU) * 4u, stream, t2);
        CP_COMMIT();
    }
    uint32_t xadr0[4], hadr0[4];
#pragma unroll
    for (int ntp = 0; ntp < 4; ++ntp) {
        xadr0[ntp] = (uint32_t)(((ntp * 16 + row_lane) * S1 + kb_off) * 4);
        hadr0[ntp] = hbyte + (uint32_t)(((ntp * 16 + row_lane) * 36 + kb_off) * 4);
    }

    for (int ba = stream; ba < NBA; ba += stride2) {
        const int b = ba >> 6;
        if (KB1 > 0) {
            int nxt = ba + stride2;
            if (nxt < NBA)
                prefetch_slice<MODE, S1>(xbyte + (uint32_t)((half * 2 + (o ^ 1)) * BUFU) * 4u, nxt, t2);
            CP_COMMIT();
            CP_WAIT1();
            BARH(barid);
        }
        const uint32_t bufB = xbyte + (uint32_t)((half * 2 + o) * BUFU) * 4u;

        float2 cg2[8];
        if (MODE <= 2) {
            const float* cgp = g_cgT + ba * 64;
#pragma unroll
            for (int nt = 0; nt < 8; ++nt)
                cg2[nt] = __ldg((const float2*)(cgp + nt * 8 + q * 2));
        }
        float acc[8][4];
#pragma unroll
        for (int nt = 0; nt < 8; ++nt)
#pragma unroll
            for (int j = 0; j < 4; ++j) acc[nt][j] = 0.f;
        if (KB1 > 0) {
            const uint4* A1 = (const uint4*)sW1f + wl * (KB1 * 32);
#pragma unroll
            for (int kt = 0; kt < KB1; ++kt) {
                uint4 Ah = A1[kt * 32 + lane];
#pragma unroll
                for (int ntp = 0; ntp < 4; ++ntp) {
                    uint32_t b0a, b1a, b0b, b1b;
                    LDM4(b0a, b1a, b0b, b1b, bufB + xadr0[ntp] + kt * 32);
                    mma16816(acc[2 * ntp],     Ah, b0a, b1a);
                    mma16816(acc[2 * ntp + 1], Ah, b0b, b1b);
                }
            }
        }
        if (MODE >= 2) {
            const float* Pb = g_P + b * 4096;
#pragma unroll
            for (int nt = 0; nt < 8; ++nt) {
                int u0 = nt * 8 + q * 2;
                float2 pa = __ldg((const float2*)(Pb + o2 * 64 + u0));
                float2 pb = __ldg((const float2*)(Pb + o2p * 64 + u0));
                acc[nt][0] += pa.x; acc[nt][1] += pa.y;
                acc[nt][2] += pb.x; acc[nt][3] += pb.y;
            }
        } else {
#pragma unroll
            for (int nt = 0; nt < 8; ++nt) {
                acc[nt][0] += bA1; acc[nt][1] += bA1;
                acc[nt][2] += bB1; acc[nt][3] += bB1;
            }
        }
        if (MODE <= 2) {
#pragma unroll
            for (int nt = 0; nt < 8; ++nt) {
                acc[nt][0] += wA * cg2[nt].x; acc[nt][1] += wA * cg2[nt].y;
                acc[nt][2] += wB * cg2[nt].x; acc[nt][3] += wB * cg2[nt].y;
            }
        }
#pragma unroll
        for (int nt = 0; nt < 8; ++nt)
#pragma unroll
            for (int j = 0; j < 4; ++j) acc[nt][j] = fmaxf(acc[nt][j], 0.0f);
        float SA, SB;
        colsum2(acc, SA, SB);

        if (!FINAL) {
            // (phi1 path)
#pragma unroll
            for (int nt = 0; nt < 8; ++nt) {
                float t0, t1, t2v, t3;
                if (wl >= 2) {
                    t0 = (SA - acc[nt][0]) * inv; t1 = (SA - acc[nt][1]) * inv;
                    t2v = (SB - acc[nt][2]) * inv; t3 = (SB - acc[nt][3]) * inv;
                } else { t0 = acc[nt][0]; t1 = acc[nt][1]; t2v = acc[nt][2]; t3 = acc[nt][3]; }
                int u0 = nt * 8 + q * 2;
                sHh[u0 * 36 + c2i]       = packh(t0, t2v);
                sHh[(u0 + 1) * 36 + c2i] = packh(t1, t3);
            }
            BARH(barid);
            float a2[8][4];
#pragma unroll
            for (int nt = 0; nt < 8; ++nt)
#pragma unroll
                for (int j = 0; j < 4; ++j) a2[nt][j] = 0.f;
#pragma unroll
            for (int kt = 0; kt < 4; ++kt) {
#pragma unroll
                for (int ntp = 0; ntp < 4; ++ntp) {
                    uint32_t b0a, b1a, b0b, b1b;
                    LDM4(b0a, b1a, b0b, b1b, hadr0[ntp] + kt * 32);
                    mma16816(a2[2 * ntp],     W2r[kt], b0a, b1a);
                    mma16816(a2[2 * ntp + 1], W2r[kt], b0b, b1b);
                }
            }
#pragma unroll
            for (int nt = 0; nt < 8; ++nt) {
                a2[nt][0] += bA2; a2[nt][1] += bA2;
                a2[nt][2] += bB2; a2[nt][3] += bB2;
            }
            float S2A, S2B;
            colsum2(a2, S2A, S2B);
            uint32_t* gout = g_msgsP + (size_t)ba * 2048;
#pragma unroll
            for (int nt = 0; nt < 8; ++nt) {
                float t0, t1, t2v, t3;
                if (wl >= 2) {
                    t0 = (S2A - a2[nt][0]) * inv; t1 = (S2A - a2[nt][1]) * inv;
                    t2v = (S2B - a2[nt][2]) * inv; t3 = (S2B - a2[nt][3]) * inv;
                } else { t0 = a2[nt][0]; t1 = a2[nt][1]; t2v = a2[nt][2]; t3 = a2[nt][3]; }
                int u0 = nt * 8 + q * 2;
                gout[u0 * 32 + c2i]       = packh(t0, t2v);
                gout[(u0 + 1) * 32 + c2i] = packh(t1, t3);
            }
            if (KB1 == 0) BARH(barid);
        } else {
#pragma unroll
            for (int nt = 0; nt < 8; ++nt) {
                float f0, f1, f2, f3;
                if (wl >= 2) {
                    f0 = (SA - acc[nt][0]) * inv; f1 = (SA - acc[nt][1]) * inv;
                    f2 = (SB - acc[nt][2]) * inv; f3 = (SB - acc[nt][3]) * inv;
                } else { f0 = acc[nt][0]; f1 = acc[nt][1]; f2 = acc[nt][2]; f3 = acc[nt][3]; }
                float p0 = w2a * f0 + w2b * f2;
                float p1 = w2a * f1 + w2b * f3;
                p0 += __shfl_xor_sync(0xffffffffu, p0, 4);
                p0 += __shfl_xor_sync(0xffffffffu, p0, 8);
                p0 += __shfl_xor_sync(0xffffffffu, p0, 16);
                p1 += __shfl_xor_sync(0xffffffffu, p1, 4);
                p1 += __shfl_xor_sync(0xffffffffu, p1, 8);
                p1 += __shfl_xor_sync(0xffffffffu, p1, 16);
                if (g == 0) {
                    int u0 = nt * 8 + q * 2;
                    sRed[half * 256 + wl * 64 + u0]     = p0;
                    sRed[half * 256 + wl * 64 + u0 + 1] = p1;
                }
            }
            BARH(barid);
            if (t2 < 64) {
                const float* R = sRed + half * 256;
                float sv = R[t2] + R[64 + t2] + R[128 + t2] + R[192 + t2];
                dout[b * 4096 + t2 * 64 + (ba & 63)] = sv + bF;
            }
            BARH(barid);
        }
        o ^= 1;
    }
}

// ---------------- FUSED gamma(i) + phi(i+1) -----------------------------------
// GMODE 2: gamma1 (X = msgs, KB4, +wcgG*cg).  GMODE 3: gammaK (X=[r,msgs], KB8).
template<int KBG, int GMODE>
__global__ void __launch_bounds__(256, 2) fused_kernel(const float* __restrict__ b2g,
                                                       const float* __restrict__ b1p,
                                                       const float* __restrict__ b2p,
                                                       int wg1off, int wg2off,
                                                       int wp1off, int wp2off,
                                                       int wcgG, int wcgP) {
    constexpr int S1 = KBG * 8 + 4;
    constexpr int BUFU = 64 * S1;
    extern __shared__ uint32_t sm[];
    uint32_t* sW1g = sm;                    // KBG*512
    uint32_t* sW1p = sW1g + KBG * 512;      // 2048
    uint32_t* sX   = sW1p + 2048;           // 2*BUFU (1 buf per half)
    uint32_t* sH   = sX + 2 * BUFU;         // 2*2304

    const int t = threadIdx.x;
    const int warp = t >> 5, lane = t & 31, q = lane & 3, g = lane >> 2;
    const int half = warp >> 2, wl = warp & 3;
    const int t2 = t & 127;
    const int o2 = wl * 16 + 2 * g, o2p = o2 + 1;
    const int c2i = wl * 8 + g;
    const float inv = 1.0f / 63.0f;
    const int barid = 1 + half;
    const int row_lane = (lane & 7) + ((lane >> 4) << 3);
    const int kb_off = ((lane >> 3) & 1) * 4;

    uint32_t smbase;
    asm("{ .reg .u64 tmp; cvta.to.shared.u64 tmp, %1; cvt.u32.u64 %0, tmp; }"
        : "=r"(smbase) : "l"(sm));
    const uint32_t xbyte = smbase + (uint32_t)(KBG * 512 + 2048) * 4u;
    const uint32_t hbyte = smbase + (uint32_t)(KBG * 512 + 2048 + 2 * BUFU + half * 2304) * 4u;
    uint32_t* sHh = sH + half * 2304;

    {
        const uint4* gw1 = (const uint4*)(g_wfrag + wg1off);
        uint4* d1 = (uint4*)sW1g;
        for (int i = t; i < KBG * 128; i += 256) d1[i] = gw1[i];
        const uint4* pw1 = (const uint4*)(g_wfrag + wp1off);
        uint4* d2 = (uint4*)sW1p;
        for (int i = t; i < 512; i += 256) d2[i] = pw1[i];
    }
    uint4 W2g[4], W2p[4];
    {
        const uint4* g2 = (const uint4*)(g_wfrag + wg2off);
        const uint4* p2 = (const uint4*)(g_wfrag + wp2off);
#pragma unroll
        for (int kt = 0; kt < 4; ++kt) {
            W2g[kt] = g2[wl * 128 + kt * 32 + lane];
            W2p[kt] = p2[wl * 128 + kt * 32 + lane];
        }
    }
    const float b2gA = __ldg(b2g + o2), b2gB = __ldg(b2g + o2p);
    const float b1pA = __ldg(b1p + o2), b1pB = __ldg(b1p + o2p);
    const float b2pA = __ldg(b2p + o2), b2pB = __ldg(b2p + o2p);
    const float wpA = g_wcg[wcgP * 64 + o2], wpB = g_wcg[wcgP * 64 + o2p];
    float wgA = 0.f, wgB = 0.f;
    if (GMODE == 2) { wgA = g_wcg[wcgG * 64 + o2]; wgB = g_wcg[wcgG * 64 + o2p]; }

    for (int i = t; i < 2 * BUFU + 2 * 2304; i += 256) sX[i] = 0;
    __syncthreads();

    const int stride2 = gridDim.x * 2;
    const int stream = blockIdx.x * 2 + half;
    const uint32_t bufB = xbyte + (uint32_t)(half * BUFU) * 4u;
    prefetch_slice<GMODE == 3 ? 3 : 2, S1>(bufB, stream, t2);
    CP_COMMIT();

    uint32_t xadr0[4], hadr0[4];
#pragma unroll
    for (int ntp = 0; ntp < 4; ++ntp) {
        xadr0[ntp] = bufB + (uint32_t)(((ntp * 16 + row_lane) * S1 + kb_off) * 4);
        hadr0[ntp] = hbyte + (uint32_t)(((ntp * 16 + row_lane) * 36 + kb_off) * 4);
    }

    for (int ba = stream; ba < NBA; ba += stride2) {
        const int b = ba >> 6;
        CP_WAIT0();
        BARH(barid);

        float2 cg2[8];
        {
            const float* cgp = g_cgT + ba * 64;
#pragma unroll
            for (int nt = 0; nt < 8; ++nt)
                cg2[nt] = __ldg((const float2*)(cgp + nt * 8 + q * 2));
        }

        // ---- gamma conv1 ----
        float acc[8][4];
#pragma unroll
        for (int nt = 0; nt < 8; ++nt)
#pragma unroll
            for (int j = 0; j < 4; ++j) acc[nt][j] = 0.f;
        {
            const uint4* A1 = (const uint4*)sW1g + wl * (KBG * 32);
#pragma unroll
            for (int kt = 0; kt < KBG; ++kt) {
                uint4 Ah = A1[kt * 32 + lane];
#pragma unroll
                for (int ntp = 0; ntp < 4; ++ntp) {
                    uint32_t b0a, b1a, b0b, b1b;
                    LDM4(b0a, b1a, b0b, b1b, xadr0[ntp] + kt * 32);
                    mma16816(acc[2 * ntp],     Ah, b0a, b1a);
                    mma16816(acc[2 * ntp + 1], Ah, b0b, b1b);
                }
            }
        }
        {
            const float* Pb = g_P + b * 4096;
#pragma unroll
            for (int nt = 0; nt < 8; ++nt) {
                int u0 = nt * 8 + q * 2;
                float2 pa = __ldg((const float2*)(Pb + o2 * 64 + u0));
                float2 pb = __ldg((const float2*)(Pb + o2p * 64 + u0));
                acc[nt][0] += pa.x; acc[nt][1] += pa.y;
                acc[nt][2] += pb.x; acc[nt][3] += pb.y;
            }
        }
        if (GMODE == 2) {
#pragma unroll
            for (int nt = 0; nt < 8; ++nt) {
                acc[nt][0] += wgA * cg2[nt].x; acc[nt][1] += wgA * cg2[nt].y;
                acc[nt][2] += wgB * cg2[nt].x; acc[nt][3] += wgB * cg2[nt].y;
            }
        }
#pragma unroll
        for (int nt = 0; nt < 8; ++nt)
#pragma unroll
            for (int j = 0; j < 4; ++j) acc[nt][j] = fmaxf(acc[nt][j], 0.0f);
        float SA, SB;
        colsum2(acc, SA, SB);
#pragma unroll
        for (int nt = 0; nt < 8; ++nt) {
            float t0, t1, t2v, t3;
            if (wl >= 2) {
                t0 = (SA - acc[nt][0]) * inv; t1 = (SA - acc[nt][1]) * inv;
                t2v = (SB - acc[nt][2]) * inv; t3 = (SB - acc[nt][3]) * inv;
            } else { t0 = acc[nt][0]; t1 = acc[nt][1]; t2v = acc[nt][2]; t3 = acc[nt][3]; }
            int u0 = nt * 8 + q * 2;
            sHh[u0 * 36 + c2i]       = packh(t0, t2v);
            sHh[(u0 + 1) * 36 + c2i] = packh(t1, t3);
        }
        BARH(barid);   // X fully consumed, H1 visible
        {
            int nxt = ba + stride2;
            if (nxt < NBA) prefetch_slice<GMODE == 3 ? 3 : 2, S1>(bufB, nxt, t2);
            CP_COMMIT();
        }

        // ---- gamma conv2 -> r ----
#pragma unroll
        for (int nt = 0; nt < 8; ++nt)
#pragma unroll
            for (int j = 0; j < 4; ++j) acc[nt][j] = 0.f;
#pragma unroll
        for (int kt = 0; kt < 4; ++kt) {
#pragma unroll
            for (int ntp = 0; ntp < 4; ++ntp) {
                uint32_t b0a, b1a, b0b, b1b;
                LDM4(b0a, b1a, b0b, b1b, hadr0[ntp] + kt * 32);
                mma16816(acc[2 * ntp],     W2g[kt], b0a, b1a);
                mma16816(acc[2 * ntp + 1], W2g[kt], b0b, b1b);
            }
        }
#pragma unroll
        for (int nt = 0; nt < 8; ++nt) {
            acc[nt][0] = fmaxf(acc[nt][0] + b2gA, 0.f);
            acc[nt][1] = fmaxf(acc[nt][1] + b2gA, 0.f);
            acc[nt][2] = fmaxf(acc[nt][2] + b2gB, 0.f);
            acc[nt][3] = fmaxf(acc[nt][3] + b2gB, 0.f);
        }
        colsum2(acc, SA, SB);
        BARH(barid);   // all H reads done before overwrite
        {
            uint32_t* gr = g_rP + (size_t)ba * 2048;
#pragma unroll
            for (int nt = 0; nt < 8; ++nt) {
                float t0, t1, t2v, t3;
                if (wl >= 2) {
                    t0 = (SA - acc[nt][0]) * inv; t1 = (SA - acc[nt][1]) * inv;
                    t2v = (SB - acc[nt][2]) * inv; t3 = (SB - acc[nt][3]) * inv;
                } else { t0 = acc[nt][0]; t1 = acc[nt][1]; t2v = acc[nt][2]; t3 = acc[nt][3]; }
                int u0 = nt * 8 + q * 2;
                uint32_t pk0 = packh(t0, t2v), pk1 = packh(t1, t3);
                sHh[u0 * 36 + c2i]       = pk0;
                sHh[(u0 + 1) * 36 + c2i] = pk1;
                gr[u0 * 32 + c2i]       = pk0;
                gr[(u0 + 1) * 32 + c2i] = pk1;
            }
        }
        BARH(barid);

        // ---- phi conv1 (input r in sHh) ----
#pragma unroll
        for (int nt = 0; nt < 8; ++nt)
#pragma unroll
            for (int j = 0; j < 4; ++j) acc[nt][j] = 0.f;
        {
            const uint4* A1 = (const uint4*)sW1p + wl * 128;
#pragma unroll
            for (int kt = 0; kt < 4; ++kt) {
                uint4 Ah = A1[kt * 32 + lane];
#pragma unroll
                for (int ntp = 0; ntp < 4; ++ntp) {
                    uint32_t b0a, b1a, b0b, b1b;
                    LDM4(b0a, b1a, b0b, b1b, hadr0[ntp] + kt * 32);
                    mma16816(acc[2 * ntp],     Ah, b0a, b1a);
                    mma16816(acc[2 * ntp + 1], Ah, b0b, b1b);
                }
            }
        }
#pragma unroll
        for (int nt = 0; nt < 8; ++nt) {
            acc[nt][0] = fmaxf(acc[nt][0] + b1pA + wpA * cg2[nt].x, 0.f);
            acc[nt][1] = fmaxf(acc[nt][1] + b1pA + wpA * cg2[nt].y, 0.f);
            acc[nt][2] = fmaxf(acc[nt][2] + b1pB + wpB * cg2[nt].x, 0.f);
            acc[nt][3] = fmaxf(acc[nt][3] + b1pB + wpB * cg2[nt].y, 0.f);
        }
        colsum2(acc, SA, SB);
        BARH(barid);
#pragma unroll
        for (int nt = 0; nt < 8; ++nt) {
            float t0, t1, t2v, t3;
            if (wl >= 2) {
                t0 = (SA - acc[nt][0]) * inv; t1 = (SA - acc[nt][1]) * inv;
                t2v = (SB - acc[nt][2]) * inv; t3 = (SB - acc[nt][3]) * inv;
            } else { t0 = acc[nt][0]; t1 = acc[nt][1]; t2v = acc[nt][2]; t3 = acc[nt][3]; }
            int u0 = nt * 8 + q * 2;
            sHh[u0 * 36 + c2i]       = packh(t0, t2v);
            sHh[(u0 + 1) * 36 + c2i] = packh(t1, t3);
        }
        BARH(barid);

        // ---- phi conv2 -> msgs ----
#pragma unroll
        for (int nt = 0; nt < 8; ++nt)
#pragma unroll
            for (int j = 0; j < 4; ++j) acc[nt][j] = 0.f;
#pragma unroll
        for (int kt = 0; kt < 4; ++kt) {
#pragma unroll
            for (int ntp = 0; ntp < 4; ++ntp) {
                uint32_t b0a, b1a, b0b, b1b;
                LDM4(b0a, b1a, b0b, b1b, hadr0[ntp] + kt * 32);
                mma16816(acc[2 * ntp],     W2p[kt], b0a, b1a);
                mma16816(acc[2 * ntp + 1], W2p[kt], b0b, b1b);
            }
        }
#pragma unroll
        for (int nt = 0; nt < 8; ++nt) {
            acc[nt][0] += b2pA; acc[nt][1] += b2pA;
            acc[nt][2] += b2pB; acc[nt][3] += b2pB;
        }
        colsum2(acc, SA, SB);
        {
            uint32_t* gm = g_msgsP + (size_t)ba * 2048;
#pragma unroll
            for (int nt = 0; nt < 8; ++nt) {
                float t0, t1, t2v, t3;
                if (wl >= 2) {
                    t0 = (SA - acc[nt][0]) * inv; t1 = (SA - acc[nt][1]) * inv;
                    t2v = (SB - acc[nt][2]) * inv; t3 = (SB - acc[nt][3]) * inv;
                } else { t0 = acc[nt][0]; t1 = acc[nt][1]; t2v = acc[nt][2]; t3 = acc[nt][3]; }
                int u0 = nt * 8 + q * 2;
                gm[u0 * 32 + c2i]       = packh(t0, t2v);
                gm[(u0 + 1) * 32 + c2i] = packh(t1, t3);
            }
        }
    }
}

// ---------------- launch -----------------------------------------------------
extern "C" void kernel_launch(void* const* d_in, const int* in_sizes, int n_in,
                              void* d_out, int out_size) {
    (void)in_sizes; (void)n_in; (void)out_size;
    const float* cg      = (const float*)d_in[0];
    const float* phi1_W1 = (const float*)d_in[1];
    const float* phi1_b1 = (const float*)d_in[2];
    const float* phi1_W2 = (const float*)d_in[3];
    const float* phi1_b2 = (const float*)d_in[4];
    const float* phiK_W1 = (const float*)d_in[5];
    const float* phiK_b1 = (const float*)d_in[6];
    const float* phiK_W2 = (const float*)d_in[7];
    const float* phiK_b2 = (const float*)d_in[8];
    const float* g1_W1   = (const float*)d_in[9];
    const float* g1_b1   = (const float*)d_in[10];
    const float* g1_W2   = (const float*)d_in[11];
    const float* g1_b2   = (const float*)d_in[12];
    const float* gK_W1   = (const float*)d_in[13];
    const float* gK_b1   = (const float*)d_in[14];
    const float* gK_W2   = (const float*)d_in[15];
    const float* gK_b2   = (const float*)d_in[16];
    const float* g5_W1   = (const float*)d_in[17];
    const float* g5_b1   = (const float*)d_in[18];
    const float* g5_W2   = (const float*)d_in[19];
    const float* g5_b2   = (const float*)d_in[20];
    float* out = (float*)d_out;

    auto smem_layer = [](int KB1, bool fin) {
        int S1 = KB1 * 8 + 4;
        int BUFU = (KB1 > 0) ? 64 * S1 : 0;
        int W1U = (KB1 > 0) ? KB1 * 512 : 0;
        return (W1U + 4 * BUFU + (fin ? 512 : 2 * 2304) + 16) * 4;
    };
    auto smem_fused = [](int KBG) {
        int S1 = KBG * 8 + 4;
        return (KBG * 512 + 2048 + 2 * 64 * S1 + 2 * 2304 + 16) * 4;
    };
    const int SM0 = smem_layer(0, false);
    const int SMF = smem_layer(8, true);
    const int SF2 = smem_fused(4);
    const int SF3 = smem_fused(8);

    cudaFuncSetAttribute(layer_kernel<0, 0, false>, cudaFuncAttributeMaxDynamicSharedMemorySize, SM0);
    cudaFuncSetAttribute(layer_kernel<8, 3, true>,  cudaFuncAttributeMaxDynamicSharedMemorySize, SMF);
    cudaFuncSetAttribute(fused_kernel<4, 2>, cudaFuncAttributeMaxDynamicSharedMemorySize, SF2);
    cudaFuncSetAttribute(fused_kernel<8, 3>, cudaFuncAttributeMaxDynamicSharedMemorySize, SF3);

    prep_kernel<<<24, 256>>>(phi1_W1, phi1_W2, phiK_W1, phiK_W2, g1_W1, g1_W2, gK_W1, gK_W2, g5_W1);
    cgt_kernel<<<128, 256>>>(cg);

    const int G = 296;

    // phi1 -> msgs1
    layer_kernel<0, 0, false><<<G, 256, SM0>>>(phi1_b1, phi1_b2, 0, O_PHI1_W2, 0, nullptr, nullptr);
    asum_kernel<<<1024, 256>>>();
    pP_kernel<<<128, 256>>>(g1_W1, g1_b1, 65, 1);
    // gamma1 + phiK0
    fused_kernel<4, 2><<<G, 256, SF2>>>(g1_b2, phiK_b1, phiK_b2,
                                        O_G1_W1, O_G1_W2, O_PHIK_W1(0), O_PHIK_W2(0), 5, 1);
    for (int i = 0; i < 3; ++i) {
        asum_kernel<<<1024, 256>>>();
        pP_kernel<<<128, 256>>>(gK_W1 + i * 8192, gK_b1 + i * 64, 128, 64);
        fused_kernel<8, 3><<<G, 256, SF3>>>(gK_b2 + i * 64, phiK_b1 + (i + 1) * 64, phiK_b2 + (i + 1) * 64,
                                            O_GK_W1(i), O_GK_W2(i), O_PHIK_W1(i + 1), O_PHIK_W2(i + 1), 0, 2 + i);
    }
    asum_kernel<<<1024, 256>>>();
    pP_kernel<<<128, 256>>>(g5_W1, g5_b1, 128, 64);
    layer_kernel<8, 3, true><<<G, 256, SMF>>>(nullptr, g5_b2, O_G5_W1, 0, 0, g5_W2, out);
}